// round 1
// baseline (speedup 1.0000x reference)
#include <cuda_runtime.h>
#include <cstdint>

// Problem constants
#define B_   4
#define H_   384
#define W_   1280
#define GH_  192                 // int(0.5 * 384)
#define N_   (GH_ * W_)          // 245760 ground points per batch
#define HW_  (H_ * W_)           // 491520
#define HYP  25                  // MAX_IT
#define NPTS 5
#define TOLF 0.1f

// Scratch (no cudaMalloc allowed)
__device__ float g_ws[B_ * HYP * 3];
__device__ int   g_cnt[B_ * HYP];
__device__ float g_bw[B_ * 3];

// ---------------------------------------------------------------------------
// Kernel 1: solve 100 3x3 least-squares systems (one per hypothesis) in fp64,
// and zero the inlier counters.
// A rows = [x, z, 1] (channels 0,2), Bm = y (channel 1 = vertical axis).
// M = A^T A + 1e-6 (scalar added to EVERY entry, matching jnp broadcast).
// ---------------------------------------------------------------------------
__global__ void k_solve(const float* __restrict__ pts, const int* __restrict__ rind) {
    int h = blockIdx.x * blockDim.x + threadIdx.x;
    if (h >= B_ * HYP) return;
    int b  = h / HYP;
    int it = h % HYP;

    const float* base = pts + (size_t)b * 3 * HW_ + (size_t)(H_ - GH_) * W_;

    double Sxx = 0, Sxz = 0, Sx = 0, Szz = 0, Sz = 0, Sxy = 0, Szy = 0, Sy = 0;
#pragma unroll
    for (int j = 0; j < NPTS; j++) {
        int n = rind[b * (HYP * NPTS) + it * NPTS + j];
        double x = (double)base[n];
        double y = (double)base[HW_ + n];
        double z = (double)base[2 * HW_ + n];
        Sxx += x * x; Sxz += x * z; Sx += x;
        Szz += z * z; Sz += z;
        Sxy += x * y; Szy += z * y; Sy += y;
    }

    const double e = 1e-6;
    double a  = Sxx + e, bb = Sxz + e, c = Sx + e;
    double d  = Szz + e, f  = Sz  + e;
    double g  = (double)NPTS + e;

    // Symmetric M = [[a,bb,c],[bb,d,f],[c,f,g]] — adjugate inverse
    double A00 = d * g - f * f;
    double A01 = c * f - bb * g;
    double A02 = bb * f - c * d;
    double det = a * A00 + bb * A01 + c * A02;
    double A11 = a * g - c * c;
    double A12 = bb * c - a * f;
    double A22 = a * d - bb * bb;
    double inv = 1.0 / det;

    double r0 = Sxy, r1 = Szy, r2 = Sy;
    double w0 = (A00 * r0 + A01 * r1 + A02 * r2) * inv;
    double w1 = (A01 * r0 + A11 * r1 + A12 * r2) * inv;
    double w2 = (A02 * r0 + A12 * r1 + A22 * r2) * inv;

    g_ws[h * 3 + 0] = (float)w0;
    g_ws[h * 3 + 1] = (float)w1;
    g_ws[h * 3 + 2] = (float)w2;
    g_cnt[h] = 0;
}

// ---------------------------------------------------------------------------
// Kernel 2: inlier counting. blockIdx.y = batch. Each thread keeps 25 local
// counters in registers, grid-strides over float4 groups of the ground region,
// then warp-reduces (redux.sync) -> shared -> one global atomic per counter.
// ---------------------------------------------------------------------------
__global__ void k_count(const float* __restrict__ pts) {
    int b = blockIdx.y;
    __shared__ float s_w[HYP * 3];
    __shared__ int   s_c[HYP];
    if (threadIdx.x < HYP * 3) s_w[threadIdx.x] = g_ws[b * HYP * 3 + threadIdx.x];
    if (threadIdx.x < HYP)     s_c[threadIdx.x] = 0;
    __syncthreads();

    const float4* xs = (const float4*)(pts + (size_t)b * 3 * HW_ + (size_t)(H_ - GH_) * W_);
    const float4* ys = xs + (HW_ / 4);
    const float4* zs = xs + 2 * (HW_ / 4);

    int c[HYP];
#pragma unroll
    for (int k = 0; k < HYP; k++) c[k] = 0;

    const int NV = N_ / 4;
    for (int v = blockIdx.x * blockDim.x + threadIdx.x; v < NV;
         v += gridDim.x * blockDim.x) {
        float4 X = xs[v];
        float4 Y = ys[v];
        float4 Z = zs[v];
#pragma unroll
        for (int k = 0; k < HYP; k++) {
            float w0 = s_w[3 * k], w1 = s_w[3 * k + 1], w2 = s_w[3 * k + 2];
            c[k] += (fabsf(fmaf(X.x, w0, fmaf(Z.x, w1, w2)) - Y.x) < TOLF);
            c[k] += (fabsf(fmaf(X.y, w0, fmaf(Z.y, w1, w2)) - Y.y) < TOLF);
            c[k] += (fabsf(fmaf(X.z, w0, fmaf(Z.z, w1, w2)) - Y.z) < TOLF);
            c[k] += (fabsf(fmaf(X.w, w0, fmaf(Z.w, w1, w2)) - Y.w) < TOLF);
        }
    }

#pragma unroll
    for (int k = 0; k < HYP; k++) {
        unsigned s = __reduce_add_sync(0xffffffffu, (unsigned)c[k]);
        if ((threadIdx.x & 31) == 0) atomicAdd(&s_c[k], (int)s);
    }
    __syncthreads();
    if (threadIdx.x < HYP) atomicAdd(&g_cnt[b * HYP + threadIdx.x], s_c[threadIdx.x]);
}

// ---------------------------------------------------------------------------
// Kernel 3: argmax (first max on ties, matching jnp.argmax), publish best_w to
// the output tail and to g_bw for the dist kernel.
// ---------------------------------------------------------------------------
__global__ void k_pick(float* __restrict__ out_bw) {
    int b = threadIdx.x;
    if (b < B_) {
        int best = 0, bc = g_cnt[b * HYP];
#pragma unroll
        for (int it = 1; it < HYP; it++) {
            int v = g_cnt[b * HYP + it];
            if (v > bc) { bc = v; best = it; }
        }
#pragma unroll
        for (int j = 0; j < 3; j++) {
            float w = g_ws[(b * HYP + best) * 3 + j];
            g_bw[b * 3 + j]   = w;
            out_bw[b * 3 + j] = w;
        }
    }
}

// ---------------------------------------------------------------------------
// Kernel 4: signed distance over ALL points (B,1,H,W), float4-vectorized.
// ---------------------------------------------------------------------------
__global__ void k_dist(const float* __restrict__ pts, float* __restrict__ out) {
    int b = blockIdx.y;
    float w0 = g_bw[b * 3 + 0];
    float w1 = g_bw[b * 3 + 1];
    float w2 = g_bw[b * 3 + 2];

    const float4* xs = (const float4*)(pts + (size_t)b * 3 * HW_);
    const float4* ys = xs + (HW_ / 4);
    const float4* zs = xs + 2 * (HW_ / 4);
    float4* o = (float4*)(out + (size_t)b * HW_);

    const int NV = HW_ / 4;
    for (int v = blockIdx.x * blockDim.x + threadIdx.x; v < NV;
         v += gridDim.x * blockDim.x) {
        float4 X = xs[v];
        float4 Y = ys[v];
        float4 Z = zs[v];
        float4 r;
        r.x = fmaf(X.x, w0, fmaf(Z.x, w1, w2)) - Y.x;
        r.y = fmaf(X.y, w0, fmaf(Z.y, w1, w2)) - Y.y;
        r.z = fmaf(X.z, w0, fmaf(Z.z, w1, w2)) - Y.z;
        r.w = fmaf(X.w, w0, fmaf(Z.w, w1, w2)) - Y.w;
        o[v] = r;
    }
}

// ---------------------------------------------------------------------------
// Launch: 4 kernels, one stream, graph-capturable (no syncs, no allocs).
// Output layout: dist (B*H*W floats) followed by best_w (B*3 floats).
// ---------------------------------------------------------------------------
extern "C" void kernel_launch(void* const* d_in, const int* in_sizes, int n_in,
                              void* d_out, int out_size) {
    const float* pts  = (const float*)d_in[0];
    const int*   rind = (const int*)d_in[1];
    float*       out  = (float*)d_out;

    k_solve<<<1, 128>>>(pts, rind);
    k_count<<<dim3(64, B_), 256>>>(pts);
    k_pick<<<1, 32>>>(out + (size_t)B_ * HW_);
    k_dist<<<dim3(128, B_), 256>>>(pts, out);
}

// round 3
// speedup vs baseline: 1.0823x; 1.0823x over previous
#include <cuda_runtime.h>
#include <cstdint>

// Problem constants
#define B_   4
#define H_   384
#define W_   1280
#define GH_  192                 // int(0.5 * 384)
#define N_   (GH_ * W_)          // 245760 ground points per batch
#define HW_  (H_ * W_)           // 491520
#define HYP  25                  // MAX_IT
#define NPTS 5
#define TOLF 0.1f

#define NV_G (N_ / 4)            // 61440 float4 groups (ground region)
#define NV_A (HW_ / 4)           // 122880 float4 groups (full image)

// Scratch (no cudaMalloc allowed)
__device__ float g_ws[B_ * HYP * 3];
__device__ int   g_cnt[B_ * HYP];

// ---------------------------------------------------------------------------
// Kernel 1: solve 100 3x3 least-squares systems (one per hypothesis) in fp64,
// and zero the inlier counters.
// A rows = [x, z, 1] (channels 0,2), Bm = y (channel 1 = vertical axis).
// M = A^T A + 1e-6 (scalar added to EVERY entry, matching jnp broadcast).
// ---------------------------------------------------------------------------
__global__ void k_solve(const float* __restrict__ pts, const int* __restrict__ rind) {
    int h = blockIdx.x * blockDim.x + threadIdx.x;
    if (h >= B_ * HYP) return;
    int b  = h / HYP;
    int it = h % HYP;

    const float* base = pts + (size_t)b * 3 * HW_ + (size_t)(H_ - GH_) * W_;

    // Gather all 15 values first (independent loads -> MLP)
    float xv[NPTS], yv[NPTS], zv[NPTS];
#pragma unroll
    for (int j = 0; j < NPTS; j++) {
        int n = rind[b * (HYP * NPTS) + it * NPTS + j];
        xv[j] = __ldg(base + n);
        yv[j] = __ldg(base + HW_ + n);
        zv[j] = __ldg(base + 2 * HW_ + n);
    }

    double Sxx = 0, Sxz = 0, Sx = 0, Szz = 0, Sz = 0, Sxy = 0, Szy = 0, Sy = 0;
#pragma unroll
    for (int j = 0; j < NPTS; j++) {
        double x = (double)xv[j], y = (double)yv[j], z = (double)zv[j];
        Sxx += x * x; Sxz += x * z; Sx += x;
        Szz += z * z; Sz += z;
        Sxy += x * y; Szy += z * y; Sy += y;
    }

    const double e = 1e-6;
    double a  = Sxx + e, bb = Sxz + e, c = Sx + e;
    double d  = Szz + e, f  = Sz  + e;
    double g  = (double)NPTS + e;

    // Symmetric M = [[a,bb,c],[bb,d,f],[c,f,g]] — adjugate inverse
    double A00 = d * g - f * f;
    double A01 = c * f - bb * g;
    double A02 = bb * f - c * d;
    double det = a * A00 + bb * A01 + c * A02;
    double A11 = a * g - c * c;
    double A12 = bb * c - a * f;
    double A22 = a * d - bb * bb;
    double inv = 1.0 / det;

    double r0 = Sxy, r1 = Szy, r2 = Sy;
    g_ws[h * 3 + 0] = (float)((A00 * r0 + A01 * r1 + A02 * r2) * inv);
    g_ws[h * 3 + 1] = (float)((A01 * r0 + A11 * r1 + A12 * r2) * inv);
    g_ws[h * 3 + 2] = (float)((A02 * r0 + A12 * r1 + A22 * r2) * inv);
    g_cnt[h] = 0;
}

// ---------------------------------------------------------------------------
// Kernel 2: inlier counting. Exact-cover grid: dim3(NV_G/256, B_), 256 thr,
// one float4 per thread (4 points x 25 hyps = 100 evals, fully ILP-exposed).
// Warp redux per hyp -> shared -> one global atomic per (block, hyp).
// ---------------------------------------------------------------------------
__global__ void __launch_bounds__(256) k_count(const float* __restrict__ pts) {
    int b = blockIdx.y;
    __shared__ float s_w[HYP * 3];
    __shared__ int   s_c[HYP];
    if (threadIdx.x < HYP * 3) s_w[threadIdx.x] = g_ws[b * HYP * 3 + threadIdx.x];
    if (threadIdx.x < HYP)     s_c[threadIdx.x] = 0;
    __syncthreads();

    const float4* xs = (const float4*)(pts + (size_t)b * 3 * HW_ + (size_t)(H_ - GH_) * W_);
    const float4* ys = xs + (HW_ / 4);
    const float4* zs = xs + 2 * (HW_ / 4);

    int v = blockIdx.x * blockDim.x + threadIdx.x;   // < NV_G by construction
    float4 X = xs[v];
    float4 Y = ys[v];
    float4 Z = zs[v];

#pragma unroll
    for (int k = 0; k < HYP; k++) {
        float w0 = s_w[3 * k], w1 = s_w[3 * k + 1], w2 = s_w[3 * k + 2];
        int c;
        c  = (fabsf(fmaf(X.x, w0, fmaf(Z.x, w1, w2)) - Y.x) < TOLF);
        c += (fabsf(fmaf(X.y, w0, fmaf(Z.y, w1, w2)) - Y.y) < TOLF);
        c += (fabsf(fmaf(X.z, w0, fmaf(Z.z, w1, w2)) - Y.z) < TOLF);
        c += (fabsf(fmaf(X.w, w0, fmaf(Z.w, w1, w2)) - Y.w) < TOLF);
        unsigned s = __reduce_add_sync(0xffffffffu, (unsigned)c);
        if ((threadIdx.x & 31) == 0) atomicAdd(&s_c[k], (int)s);
    }
    __syncthreads();
    if (threadIdx.x < HYP) atomicAdd(&g_cnt[b * HYP + threadIdx.x], s_c[threadIdx.x]);
}

// ---------------------------------------------------------------------------
// Kernel 3: fused pick + signed distance over ALL points (B,1,H,W).
// Every block redundantly computes the 25-way argmax (L2-resident, ~25 instrs;
// first-max tie rule matches jnp.argmax). Block (0,b) also writes best_w.
// Exact-cover grid: dim3(NV_A/256, B_), one float4 per thread, no loop.
// ---------------------------------------------------------------------------
__global__ void __launch_bounds__(256) k_dist(const float* __restrict__ pts,
                                              float* __restrict__ out,
                                              float* __restrict__ out_bw) {
    int b = blockIdx.y;

    int best = 0, bc = g_cnt[b * HYP];
#pragma unroll
    for (int it = 1; it < HYP; it++) {
        int v = g_cnt[b * HYP + it];
        if (v > bc) { bc = v; best = it; }
    }
    const float* wp = &g_ws[(b * HYP + best) * 3];
    float w0 = wp[0], w1 = wp[1], w2 = wp[2];

    if (blockIdx.x == 0 && threadIdx.x < 3) out_bw[b * 3 + threadIdx.x] = wp[threadIdx.x];

    const float4* xs = (const float4*)(pts + (size_t)b * 3 * HW_);
    const float4* ys = xs + (HW_ / 4);
    const float4* zs = xs + 2 * (HW_ / 4);
    float4* o = (float4*)(out + (size_t)b * HW_);

    int v = blockIdx.x * blockDim.x + threadIdx.x;   // < NV_A by construction
    float4 X = xs[v];
    float4 Y = ys[v];
    float4 Z = zs[v];
    float4 r;
    r.x = fmaf(X.x, w0, fmaf(Z.x, w1, w2)) - Y.x;
    r.y = fmaf(X.y, w0, fmaf(Z.y, w1, w2)) - Y.y;
    r.z = fmaf(X.z, w0, fmaf(Z.z, w1, w2)) - Y.z;
    r.w = fmaf(X.w, w0, fmaf(Z.w, w1, w2)) - Y.w;
    o[v] = r;
}

// ---------------------------------------------------------------------------
// Launch: 3 kernels, one stream, graph-capturable (no syncs, no allocs).
// Output layout: dist (B*H*W floats) followed by best_w (B*3 floats).
// ---------------------------------------------------------------------------
extern "C" void kernel_launch(void* const* d_in, const int* in_sizes, int n_in,
                              void* d_out, int out_size) {
    const float* pts  = (const float*)d_in[0];
    const int*   rind = (const int*)d_in[1];
    float*       out  = (float*)d_out;

    k_solve<<<1, 128>>>(pts, rind);
    k_count<<<dim3(NV_G / 256, B_), 256>>>(pts);
    k_dist<<<dim3(NV_A / 256, B_), 256>>>(pts, out, out + (size_t)B_ * HW_);
}